// round 16
// baseline (speedup 1.0000x reference)
#include <cuda_runtime.h>
#include <cuda_bf16.h>
#include <cstdint>

#define NNODES 100000
#define NEDGES 1600000
#define FEATS  256
#define MAXK   32
#define NCHUNK 8             // 256 / 32
#define AP     80            // padded smem row stride (bytes) for 32 bf16
#define APA    5120          // A plane bytes: 64 rows * AP
#define APB    20480         // B plane bytes: 256 rows * AP
#define SSZ    51200         // stage: Ahi|Alo (5120 ea) + Bhi|Blo (20480 ea)
#define SMEM_DYN 102400      // 2 stages; epilogue overlay 64*258*4=66048 fits

// ---------------- scratch (no allocations allowed) ----------------
__device__ unsigned        g_pk[NNODES * MAXK];   // packed: (val_bits & 0xFFFFFF00) | col
__device__ int             g_deg[NNODES];
__device__ int             g_off[NNODES + 1];
__device__ int             g_cur[NNODES];
__device__ int             g_csr[NEDGES];
__device__ int             g_is64;
__device__ int             g_bsum[128];
__device__ int             g_bpre[128];
__device__ __nv_bfloat16   g_bhi[512 * 256];   // [n 0..511][k] = W^T; n<256 self, n>=256 neigh
__device__ __nv_bfloat16   g_blo[512 * 256];

// ---------------- helpers ----------------
__device__ __forceinline__ uint32_t smem_u32(const void* p) {
    uint32_t a;
    asm("{ .reg .u64 t; cvta.to.shared.u64 t, %1; cvt.u32.u64 %0, t; }" : "=r"(a) : "l"(p));
    return a;
}
__device__ __forceinline__ void cp16(uint32_t dst, const void* src) {
    asm volatile("cp.async.cg.shared.global [%0], [%1], 16;" :: "r"(dst), "l"(src));
}
#define CP_COMMIT() asm volatile("cp.async.commit_group;" ::: "memory")
#define CP_WAIT(n)  asm volatile("cp.async.wait_group %0;" :: "n"(n) : "memory")

__device__ __forceinline__ void ldm4(uint32_t r[4], uint32_t addr) {
    asm volatile("ldmatrix.sync.aligned.m8n8.x4.shared.b16 {%0,%1,%2,%3}, [%4];"
                 : "=r"(r[0]), "=r"(r[1]), "=r"(r[2]), "=r"(r[3]) : "r"(addr));
}
__device__ __forceinline__ void mma_bf16(float* c, const uint32_t* a, const uint32_t* b) {
    asm volatile("mma.sync.aligned.m16n8k16.row.col.f32.bf16.bf16.f32 "
                 "{%0,%1,%2,%3}, {%4,%5,%6,%7}, {%8,%9}, {%0,%1,%2,%3};"
                 : "+f"(c[0]), "+f"(c[1]), "+f"(c[2]), "+f"(c[3])
                 : "r"(a[0]), "r"(a[1]), "r"(a[2]), "r"(a[3]), "r"(b[0]), "r"(b[1]));
}
__device__ __forceinline__ uint32_t pack2(float x, float y) {
    uint32_t lo = (uint32_t)__bfloat16_as_ushort(__float2bfloat16_rn(x));
    uint32_t hi = (uint32_t)__bfloat16_as_ushort(__float2bfloat16_rn(y));
    return lo | (hi << 16);
}

// ---------------- dtype detection for src/dst ----------------
__global__ void k_detect(const void* src) {
    if (threadIdx.x == 0 && blockIdx.x == 0) {
        const long long* p = (const long long*)src;
        int ok = 1;
        for (int i = 0; i < 64; i++) {
            long long v = p[i];
            if (v < 0 || v >= NNODES) { ok = 0; break; }
        }
        g_is64 = ok;
    }
}
__device__ __forceinline__ int ld_idx(const void* p, int i) {
    if (g_is64) return (int)((const long long*)p)[i];
    return ((const int*)p)[i];
}

// ---------------- weight prep: W^T + bf16 hi/lo split (+deg zeroing fused) ----------------
__global__ void k_prep_w(const float* __restrict__ Ws, const float* __restrict__ Wn) {
    int i = blockIdx.x * 256 + threadIdx.x;   // i = n*256 + k
    if (i < NNODES) g_deg[i] = 0;             // fused zero_deg (131072 >= NNODES)
    if (i >= 512 * 256) return;
    int k = i & 255;
    int n = i >> 8;
    float x = (n >= 256) ? Wn[k * 256 + (n - 256)] : Ws[k * 256 + n];
    __nv_bfloat16 h = __float2bfloat16_rn(x);
    float l = x - __bfloat162float(h);
    g_bhi[i] = h;
    g_blo[i] = __float2bfloat16_rn(l);
}

// ---------------- degree / scan / scatter ----------------
__global__ void k_count(const void* dst) {
    int e = blockIdx.x * blockDim.x + threadIdx.x;
    if (e < NEDGES) atomicAdd(&g_deg[ld_idx(dst, e)], 1);
}
__global__ void k_scan1() {
    __shared__ int sh[1024];
    int t = threadIdx.x;
    int i = blockIdx.x * 1024 + t;
    int v = (i < NNODES) ? g_deg[i] : 0;
    sh[t] = v; __syncthreads();
    for (int off = 1; off < 1024; off <<= 1) {
        int x = (t >= off) ? sh[t - off] : 0;
        __syncthreads();
        sh[t] += x;
        __syncthreads();
    }
    if (i < NNODES) g_off[i] = sh[t] - v;
    if (t == 1023) g_bsum[blockIdx.x] = sh[1023];
}
__global__ void k_scan2() {
    __shared__ int sh[128];
    int t = threadIdx.x;
    int v = (t < 98) ? g_bsum[t] : 0;
    sh[t] = v; __syncthreads();
    for (int off = 1; off < 128; off <<= 1) {
        int x = (t >= off) ? sh[t - off] : 0;
        __syncthreads();
        sh[t] += x;
        __syncthreads();
    }
    g_bpre[t] = sh[t] - v;
    if (t == 127) g_off[NNODES] = sh[127];
}
__global__ void k_scan3() {
    int i = blockIdx.x * 1024 + threadIdx.x;
    if (i < NNODES) {
        int o = g_off[i] + g_bpre[blockIdx.x];
        g_off[i] = o;
        g_cur[i] = o;
    }
}
__global__ void k_scatter(const void* src, const void* dst) {
    int e = blockIdx.x * blockDim.x + threadIdx.x;
    if (e < NEDGES) {
        int s = ld_idx(src, e);
        int d = ld_idx(dst, e);
        int pos = atomicAdd(&g_cur[d], 1);
        g_csr[pos] = s;
    }
}

// ---------------- fused GEMM (+topk for neigh): C[64 x 256] per CTA ----------------
// grid (2, 1564): x=0 -> h_self -> out; x=1 -> h_neigh -> in-place top-32.
// Adjacent x-pairs share the same A rows -> second CTA hits L2 for feat.
// A fp32 prefetched into regs at TOP of iter (latency hidden by MMAs),
// converted bf16 hi/lo + STS at bottom. 2 CTAs/SM.
__global__ __launch_bounds__(256, 2) void k_gemm(const float* __restrict__ feat,
                                                 float* __restrict__ out) {
    extern __shared__ char sm[];
    uint32_t sb = smem_u32(sm);
    int t = threadIdx.x, lane = t & 31, w = t >> 5;
    int m = blockIdx.x;
    int rowBase = blockIdx.y * 64;
    int warpM = w & 1, warpN = w >> 1;

    // ---- A mapping: row = t>>2 (0..63), seg = t&3 (8 fp32 cols) ----
    int arow = t >> 2, asg = t & 3;
    int grA = rowBase + arow;
    bool aOK = grA < NNODES;
    const float* pA = feat + (size_t)grA * FEATS + asg * 8;   // advance 32 floats/chunk
    uint32_t dofA = (uint32_t)(arow * AP + asg * 16);

    // ---- B cp.async: single base + constant strides (reg-lean) ----
    int bn0 = t >> 2, bs0 = t & 3;
    size_t bOff0 = ((size_t)(m * 256 + bn0) * 256 + bs0 * 8) * 2;
    const char* pBh0 = (const char*)g_bhi + bOff0;
    const char* pBl0 = (const char*)g_blo + bOff0;
    uint32_t dofB0 = (uint32_t)(bn0 * AP + bs0 * 16);

    float aR[8];
    auto ldA = [&]() {                       // fp32 LDG for next-needed chunk
        float4 v0 = aOK ? *(const float4*)pA       : make_float4(0.f, 0.f, 0.f, 0.f);
        float4 v1 = aOK ? *(const float4*)(pA + 4) : make_float4(0.f, 0.f, 0.f, 0.f);
        aR[0] = v0.x; aR[1] = v0.y; aR[2] = v0.z; aR[3] = v0.w;
        aR[4] = v1.x; aR[5] = v1.y; aR[6] = v1.z; aR[7] = v1.w;
        pA += 32;
    };
    auto stA = [&](int stage) {              // convert + STS from aR
        char* stp = sm + stage * SSZ;
        float hs[8];
#pragma unroll
        for (int q = 0; q < 8; q++) hs[q] = __bfloat162float(__float2bfloat16_rn(aR[q]));
        *(uint4*)(stp + dofA) = make_uint4(pack2(hs[0], hs[1]), pack2(hs[2], hs[3]),
                                           pack2(hs[4], hs[5]), pack2(hs[6], hs[7]));
        *(uint4*)(stp + APA + dofA) = make_uint4(
            pack2(aR[0] - hs[0], aR[1] - hs[1]), pack2(aR[2] - hs[2], aR[3] - hs[3]),
            pack2(aR[4] - hs[4], aR[5] - hs[5]), pack2(aR[6] - hs[6], aR[7] - hs[7]));
    };
    auto cpB = [&](int stage) {
        uint32_t st = sb + stage * SSZ + 2 * APA;
#pragma unroll
        for (int i = 0; i < 4; i++) {
            cp16(st + dofB0 + i * 5120,       pBh0 + i * 32768);
            cp16(st + APB + dofB0 + i * 5120, pBl0 + i * 32768);
        }
        CP_COMMIT();
        pBh0 += 64; pBl0 += 64;
    };

    float acc[2][8][4];
#pragma unroll
    for (int mf = 0; mf < 2; mf++)
#pragma unroll
        for (int nf = 0; nf < 8; nf++)
#pragma unroll
            for (int q = 0; q < 4; q++) acc[mf][nf][q] = 0.f;

    // prologue: 2-stage
    ldA(); stA(0); cpB(0);
    ldA(); stA(1); cpB(1);

    uint32_t aoff = (uint32_t)((lane & 7) + ((lane & 8) ? 8 : 0)) * AP + ((lane & 16) ? 16 : 0);
    uint32_t boff = (uint32_t)((lane & 7) + ((lane & 16) ? 8 : 0)) * AP + ((lane & 8) ? 16 : 0);

    for (int c = 0; c < NCHUNK; c++) {
        if (c >= NCHUNK - 2) { CP_WAIT(0); } else { CP_WAIT(1); }
        __syncthreads();

        if (c + 2 < NCHUNK) ldA();           // LDG for chunk c+2; hidden by MMAs below

        uint32_t st = sb + (c & 1) * SSZ;
#pragma unroll
        for (int ks = 0; ks < 2; ks++) {
            uint32_t ahf[2][4], alf[2][4];
#pragma unroll
            for (int mf = 0; mf < 2; mf++) {
                uint32_t ra = st + (uint32_t)(warpM * 32 + mf * 16) * AP + aoff + ks * 32;
                ldm4(ahf[mf], ra);
                ldm4(alf[mf], ra + APA);
            }
#pragma unroll
            for (int p = 0; p < 4; p++) {
                uint32_t rbn = st + 2 * APA + (uint32_t)(warpN * 64 + p * 16) * AP + boff + ks * 32;
                uint32_t rh[4], rl[4];
                ldm4(rh, rbn);
                ldm4(rl, rbn + APB);
                uint32_t bh0[2] = { rh[0], rh[1] }, bh1[2] = { rh[2], rh[3] };
                uint32_t bl0[2] = { rl[0], rl[1] }, bl1[2] = { rl[2], rl[3] };
                mma_bf16(acc[0][2*p],   ahf[0], bh0);
                mma_bf16(acc[1][2*p],   ahf[1], bh0);
                mma_bf16(acc[0][2*p+1], ahf[0], bh1);
                mma_bf16(acc[1][2*p+1], ahf[1], bh1);

                mma_bf16(acc[0][2*p],   ahf[0], bl0);
                mma_bf16(acc[1][2*p],   ahf[1], bl0);
                mma_bf16(acc[0][2*p+1], ahf[0], bl1);
                mma_bf16(acc[1][2*p+1], ahf[1], bl1);

                mma_bf16(acc[0][2*p],   alf[0], bh0);
                mma_bf16(acc[1][2*p],   alf[1], bh0);
                mma_bf16(acc[0][2*p+1], alf[0], bh1);
                mma_bf16(acc[1][2*p+1], alf[1], bh1);
            }
        }

        if (c + 2 < NCHUNK) {
            __syncthreads();           // all LDSM reads of this stage done
            stA(c & 1);                // convert prefetched aR into freed stage
            cpB(c & 1);
        }
    }

    int g = lane >> 2, tt = lane & 3;
    if (m == 0) {
        // h_self straight to out
#pragma unroll
        for (int mf = 0; mf < 2; mf++)
#pragma unroll
            for (int nf = 0; nf < 8; nf++) {
                int r0 = rowBase + warpM * 32 + mf * 16 + g;
                int col = warpN * 64 + nf * 8 + tt * 2;
                if (r0 < NNODES)
                    *(float2*)&out[(size_t)r0 * 256 + col] = make_float2(acc[mf][nf][0], acc[mf][nf][1]);
                if (r0 + 8 < NNODES)
                    *(float2*)&out[(size_t)(r0 + 8) * 256 + col] = make_float2(acc[mf][nf][2], acc[mf][nf][3]);
            }
        return;
    }

    // h_neigh: stage into smem overlay, then top-32 via sorted shift-register + REDUX
    __syncthreads();
    float* stg = (float*)sm;                 // 64 rows x stride 258 floats
#pragma unroll
    for (int mf = 0; mf < 2; mf++)
#pragma unroll
        for (int nf = 0; nf < 8; nf++) {
            int lr = warpM * 32 + mf * 16 + g;
            int col = warpN * 64 + nf * 8 + tt * 2;
            *(float2*)&stg[(size_t)lr * 258 + col]       = make_float2(acc[mf][nf][0], acc[mf][nf][1]);
            *(float2*)&stg[(size_t)(lr + 8) * 258 + col] = make_float2(acc[mf][nf][2], acc[mf][nf][3]);
        }
    __syncthreads();

    int lr0 = w * 8;
    unsigned sk[8][8], win[8];
#define CE(r,i,j) { unsigned _a = sk[r][i], _b = sk[r][j]; \
                    sk[r][i] = _a > _b ? _a : _b; sk[r][j] = _a > _b ? _b : _a; }
#pragma unroll
    for (int r = 0; r < 8; r++) {
#pragma unroll
        for (int j = 0; j < 8; j++) {
            int col = j * 32 + lane;
            unsigned u = __float_as_uint(stg[(size_t)(lr0 + r) * 258 + col]);
            unsigned key = (u & 0x80000000u) ? ~u : (u | 0x80000000u);
            sk[r][j] = (key & 0xFFFFFF00u) | (255u - (unsigned)col);
        }
        // Batcher odd-even merge sort, 19 CE, descending
        CE(r,0,1) CE(r,2,3) CE(r,4,5) CE(r,6,7)
        CE(r,0,2) CE(r,1,3) CE(r,4,6) CE(r,5,7)
        CE(r,1,2) CE(r,5,6)
        CE(r,0,4) CE(r,1,5) CE(r,2,6) CE(r,3,7)
        CE(r,2,4) CE(r,3,5)
        CE(r,1,2) CE(r,3,4) CE(r,5,6)
        win[r] = 0;
    }
#undef CE

#pragma unroll 1
    for (int it = 0; it < MAXK; it++) {
        unsigned gm[8];
#pragma unroll
        for (int r = 0; r < 8; r++) gm[r] = __reduce_max_sync(0xFFFFFFFFu, sk[r][0]);
#pragma unroll
        for (int r = 0; r < 8; r++) {
            win[r] = (lane == it) ? gm[r] : win[r];
            bool own = (sk[r][0] == gm[r]);
#pragma unroll
            for (int j = 0; j < 7; j++) sk[r][j] = own ? sk[r][j + 1] : sk[r][j];
            sk[r][7] = own ? 0u : sk[r][7];
        }
    }

    // store packed (val_bits & 0xFFFFFF00) | col — ONE 4-byte word per entry
#pragma unroll
    for (int r = 0; r < 8; r++) {
        int grow = rowBase + lr0 + r;
        if (grow < NNODES) {
            unsigned col = 255u - (win[r] & 0xFFu);
            unsigned kk = win[r] & 0xFFFFFF00u;
            unsigned u = (kk & 0x80000000u) ? (kk & 0x7FFFFFFFu) : ~kk;
            g_pk[(size_t)grow * MAXK + lane] = (u & 0xFFFFFF00u) | col;
        }
    }
}

// ---------------- aggregation: one warp per dst node, packed single-word gather ----------------
__global__ __launch_bounds__(512) void k_aggregate(float* __restrict__ out) {
    __shared__ float acc[16][256];
    int w = threadIdx.x >> 5;
    int lane = threadIdx.x & 31;
    int v = blockIdx.x * 16 + w;
    if (v >= NNODES) return;

#pragma unroll
    for (int j = 0; j < 8; j++) acc[w][lane + 32 * j] = 0.f;
    __syncwarp();

    int beg = g_off[v];
    int end = g_off[v + 1];
    int c = 0; float vv = 0.f;
    if (beg < end) {
        int s = g_csr[beg];
        unsigned pk = g_pk[(size_t)s * MAXK + lane];
        c  = (int)(pk & 0xFFu);
        vv = __uint_as_float(pk & 0xFFFFFF00u);
    }
    for (int e = beg; e < end; e++) {
        int nc = 0; float nv = 0.f;
        if (e + 1 < end) {
            int s2 = g_csr[e + 1];
            unsigned pk = g_pk[(size_t)s2 * MAXK + lane];
            nc = (int)(pk & 0xFFu);
            nv = __uint_as_float(pk & 0xFFFFFF00u);
        }
        acc[w][c] += vv;          // distinct addrs within edge -> race-free
        __syncwarp();             // order before next edge's RMW
        c = nc; vv = nv;
    }

    int deg = end - beg;
    float inv = 1.0f / (float)(deg > 0 ? deg : 1);
    size_t bo = (size_t)v * FEATS;
#pragma unroll
    for (int j = 0; j < 8; j++) {
        int cc = lane + 32 * j;
        out[bo + cc] += acc[w][cc] * inv;
    }
}

// ---------------- launch: fork CSR-build chain onto a side stream; join before aggregate ----------------
extern "C" void kernel_launch(void* const* d_in, const int* in_sizes, int n_in,
                              void* d_out, int out_size) {
    const float* feat = (const float*)d_in[0];
    const float* Ws   = (const float*)d_in[1];
    const float* Wn   = (const float*)d_in[2];
    const void*  src  = d_in[3];
    const void*  dst  = d_in[4];
    float* out = (float*)d_out;

    cudaFuncSetAttribute(k_gemm, cudaFuncAttributeMaxDynamicSharedMemorySize, SMEM_DYN);

    cudaStream_t s2;
    cudaStreamCreateWithFlags(&s2, cudaStreamNonBlocking);
    cudaEvent_t eFork, eJoin;
    cudaEventCreateWithFlags(&eFork, cudaEventDisableTiming);
    cudaEventCreateWithFlags(&eJoin, cudaEventDisableTiming);

    // main chain (stream 0 / capture stream)
    k_prep_w<<<512, 256>>>(Ws, Wn);                           // 1st (also zeroes g_deg)

    // fork side chain (needs g_deg zeroed -> event after prep_w)
    cudaEventRecord(eFork, 0);
    cudaStreamWaitEvent(s2, eFork, 0);
    k_detect<<<1, 64, 0, s2>>>(src);                          // 2nd
    k_count<<<(NEDGES + 255) / 256, 256, 0, s2>>>(dst);       // 3rd

    dim3 gg(2, 1564);
    k_gemm<<<gg, 256, SMEM_DYN>>>(feat, out);                 // 4th launch (profiled)

    k_scan1<<<98, 1024, 0, s2>>>();
    k_scan2<<<1, 128, 0, s2>>>();
    k_scan3<<<98, 1024, 0, s2>>>();
    k_scatter<<<(NEDGES + 255) / 256, 256, 0, s2>>>(src, dst);

    // join: aggregate needs g_pk (stream 0) + g_csr/g_off (s2)
    cudaEventRecord(eJoin, s2);
    cudaStreamWaitEvent(0, eJoin, 0);
    k_aggregate<<<(NNODES + 15) / 16, 512>>>(out);

    cudaEventDestroy(eFork);
    cudaEventDestroy(eJoin);
    cudaStreamDestroy(s2);
}

// round 17
// speedup vs baseline: 1.5012x; 1.5012x over previous
#include <cuda_runtime.h>
#include <cuda_bf16.h>
#include <cstdint>

#define NNODES 100000
#define NEDGES 1600000
#define FEATS  256
#define MAXK   32
#define NCHUNK 8             // 256 / 32
#define AP     80            // padded smem row stride (bytes) for 32 bf16
#define APA    5120          // A plane bytes: 64 rows * AP
#define APB    20480         // B plane bytes: 256 rows * AP
#define SSZ    51200         // stage: Ahi|Alo (5120 ea) + Bhi|Blo (20480 ea)
#define SMEM_DYN 102400      // 2 stages; epilogue overlay 64*258*4=66048 fits

// ---------------- scratch (no allocations allowed) ----------------
__device__ unsigned        g_pk[NNODES * MAXK];   // packed: (val_bits & 0xFFFFFF00) | col
__device__ int             g_deg[NNODES];
__device__ int             g_off[NNODES + 1];
__device__ int             g_cur[NNODES];
__device__ int             g_csr[NEDGES];
__device__ int             g_is64;
__device__ int             g_bsum[128];
__device__ int             g_bpre[128];
__device__ __nv_bfloat16   g_bhi[512 * 256];   // [n 0..511][k] = W^T; n<256 self, n>=256 neigh
__device__ __nv_bfloat16   g_blo[512 * 256];

// ---------------- helpers ----------------
__device__ __forceinline__ uint32_t smem_u32(const void* p) {
    uint32_t a;
    asm("{ .reg .u64 t; cvta.to.shared.u64 t, %1; cvt.u32.u64 %0, t; }" : "=r"(a) : "l"(p));
    return a;
}
__device__ __forceinline__ void cp16(uint32_t dst, const void* src) {
    asm volatile("cp.async.cg.shared.global [%0], [%1], 16;" :: "r"(dst), "l"(src));
}
#define CP_COMMIT() asm volatile("cp.async.commit_group;" ::: "memory")
#define CP_WAIT(n)  asm volatile("cp.async.wait_group %0;" :: "n"(n) : "memory")

__device__ __forceinline__ void ldm4(uint32_t r[4], uint32_t addr) {
    asm volatile("ldmatrix.sync.aligned.m8n8.x4.shared.b16 {%0,%1,%2,%3}, [%4];"
                 : "=r"(r[0]), "=r"(r[1]), "=r"(r[2]), "=r"(r[3]) : "r"(addr));
}
__device__ __forceinline__ void mma_bf16(float* c, const uint32_t* a, const uint32_t* b) {
    asm volatile("mma.sync.aligned.m16n8k16.row.col.f32.bf16.bf16.f32 "
                 "{%0,%1,%2,%3}, {%4,%5,%6,%7}, {%8,%9}, {%0,%1,%2,%3};"
                 : "+f"(c[0]), "+f"(c[1]), "+f"(c[2]), "+f"(c[3])
                 : "r"(a[0]), "r"(a[1]), "r"(a[2]), "r"(a[3]), "r"(b[0]), "r"(b[1]));
}
__device__ __forceinline__ uint32_t pack2(float x, float y) {
    uint32_t lo = (uint32_t)__bfloat16_as_ushort(__float2bfloat16_rn(x));
    uint32_t hi = (uint32_t)__bfloat16_as_ushort(__float2bfloat16_rn(y));
    return lo | (hi << 16);
}

// ---------------- dtype detection for src/dst ----------------
__global__ void k_detect(const void* src) {
    if (threadIdx.x == 0 && blockIdx.x == 0) {
        const long long* p = (const long long*)src;
        int ok = 1;
        for (int i = 0; i < 64; i++) {
            long long v = p[i];
            if (v < 0 || v >= NNODES) { ok = 0; break; }
        }
        g_is64 = ok;
    }
}
__device__ __forceinline__ int ld_idx(const void* p, int i) {
    if (g_is64) return (int)((const long long*)p)[i];
    return ((const int*)p)[i];
}

// ---------------- weight prep: W^T + bf16 hi/lo split (+deg zeroing fused) ----------------
__global__ void k_prep_w(const float* __restrict__ Ws, const float* __restrict__ Wn) {
    int i = blockIdx.x * 256 + threadIdx.x;   // i = n*256 + k
    if (i < NNODES) g_deg[i] = 0;             // fused zero_deg (131072 >= NNODES)
    if (i >= 512 * 256) return;
    int k = i & 255;
    int n = i >> 8;
    float x = (n >= 256) ? Wn[k * 256 + (n - 256)] : Ws[k * 256 + n];
    __nv_bfloat16 h = __float2bfloat16_rn(x);
    float l = x - __bfloat162float(h);
    g_bhi[i] = h;
    g_blo[i] = __float2bfloat16_rn(l);
}

// ---------------- degree / scan / scatter ----------------
__global__ void k_count(const void* dst) {
    int e = blockIdx.x * blockDim.x + threadIdx.x;
    if (e < NEDGES) atomicAdd(&g_deg[ld_idx(dst, e)], 1);
}
__global__ void k_scan1() {
    __shared__ int sh[1024];
    int t = threadIdx.x;
    int i = blockIdx.x * 1024 + t;
    int v = (i < NNODES) ? g_deg[i] : 0;
    sh[t] = v; __syncthreads();
    for (int off = 1; off < 1024; off <<= 1) {
        int x = (t >= off) ? sh[t - off] : 0;
        __syncthreads();
        sh[t] += x;
        __syncthreads();
    }
    if (i < NNODES) g_off[i] = sh[t] - v;
    if (t == 1023) g_bsum[blockIdx.x] = sh[1023];
}
__global__ void k_scan2() {
    __shared__ int sh[128];
    int t = threadIdx.x;
    int v = (t < 98) ? g_bsum[t] : 0;
    sh[t] = v; __syncthreads();
    for (int off = 1; off < 128; off <<= 1) {
        int x = (t >= off) ? sh[t - off] : 0;
        __syncthreads();
        sh[t] += x;
        __syncthreads();
    }
    g_bpre[t] = sh[t] - v;
    if (t == 127) g_off[NNODES] = sh[127];
}
__global__ void k_scan3() {
    int i = blockIdx.x * 1024 + threadIdx.x;
    if (i < NNODES) {
        int o = g_off[i] + g_bpre[blockIdx.x];
        g_off[i] = o;
        g_cur[i] = o;
    }
}
__global__ void k_scatter(const void* src, const void* dst) {
    int e = blockIdx.x * blockDim.x + threadIdx.x;
    if (e < NEDGES) {
        int s = ld_idx(src, e);
        int d = ld_idx(dst, e);
        int pos = atomicAdd(&g_cur[d], 1);
        g_csr[pos] = s;
    }
}

// ---------------- fused GEMM (+topk for neigh): C[64 x 256] per CTA ----------------
// grid (2, 1564): x=0 -> h_self -> out; x=1 -> h_neigh -> in-place top-32.
// Adjacent x-pairs share the same A rows -> second CTA hits L2 for feat.
// A fp32 prefetched into regs at TOP of iter (latency hidden by MMAs),
// converted bf16 hi/lo + STS at bottom. 2 CTAs/SM.
__global__ __launch_bounds__(256, 2) void k_gemm(const float* __restrict__ feat,
                                                 float* __restrict__ out) {
    extern __shared__ char sm[];
    uint32_t sb = smem_u32(sm);
    int t = threadIdx.x, lane = t & 31, w = t >> 5;
    int m = blockIdx.x;
    int rowBase = blockIdx.y * 64;
    int warpM = w & 1, warpN = w >> 1;

    // ---- A mapping: row = t>>2 (0..63), seg = t&3 (8 fp32 cols) ----
    int arow = t >> 2, asg = t & 3;
    int grA = rowBase + arow;
    bool aOK = grA < NNODES;
    const float* pA = feat + (size_t)grA * FEATS + asg * 8;   // advance 32 floats/chunk
    uint32_t dofA = (uint32_t)(arow * AP + asg * 16);

    // ---- B cp.async: single base + constant strides (reg-lean) ----
    int bn0 = t >> 2, bs0 = t & 3;
    size_t bOff0 = ((size_t)(m * 256 + bn0) * 256 + bs0 * 8) * 2;
    const char* pBh0 = (const char*)g_bhi + bOff0;
    const char* pBl0 = (const char*)g_blo + bOff0;
    uint32_t dofB0 = (uint32_t)(bn0 * AP + bs0 * 16);

    float aR[8];
    auto ldA = [&]() {                       // fp32 LDG for next-needed chunk
        float4 v0 = aOK ? *(const float4*)pA       : make_float4(0.f, 0.f, 0.f, 0.f);
        float4 v1 = aOK ? *(const float4*)(pA + 4) : make_float4(0.f, 0.f, 0.f, 0.f);
        aR[0] = v0.x; aR[1] = v0.y; aR[2] = v0.z; aR[3] = v0.w;
        aR[4] = v1.x; aR[5] = v1.y; aR[6] = v1.z; aR[7] = v1.w;
        pA += 32;
    };
    auto stA = [&](int stage) {              // convert + STS from aR
        char* stp = sm + stage * SSZ;
        float hs[8];
#pragma unroll
        for (int q = 0; q < 8; q++) hs[q] = __bfloat162float(__float2bfloat16_rn(aR[q]));
        *(uint4*)(stp + dofA) = make_uint4(pack2(hs[0], hs[1]), pack2(hs[2], hs[3]),
                                           pack2(hs[4], hs[5]), pack2(hs[6], hs[7]));
        *(uint4*)(stp + APA + dofA) = make_uint4(
            pack2(aR[0] - hs[0], aR[1] - hs[1]), pack2(aR[2] - hs[2], aR[3] - hs[3]),
            pack2(aR[4] - hs[4], aR[5] - hs[5]), pack2(aR[6] - hs[6], aR[7] - hs[7]));
    };
    auto cpB = [&](int stage) {
        uint32_t st = sb + stage * SSZ + 2 * APA;
#pragma unroll
        for (int i = 0; i < 4; i++) {
            cp16(st + dofB0 + i * 5120,       pBh0 + i * 32768);
            cp16(st + APB + dofB0 + i * 5120, pBl0 + i * 32768);
        }
        CP_COMMIT();
        pBh0 += 64; pBl0 += 64;
    };

    float acc[2][8][4];
#pragma unroll
    for (int mf = 0; mf < 2; mf++)
#pragma unroll
        for (int nf = 0; nf < 8; nf++)
#pragma unroll
            for (int q = 0; q < 4; q++) acc[mf][nf][q] = 0.f;

    // prologue: 2-stage
    ldA(); stA(0); cpB(0);
    ldA(); stA(1); cpB(1);

    uint32_t aoff = (uint32_t)((lane & 7) + ((lane & 8) ? 8 : 0)) * AP + ((lane & 16) ? 16 : 0);
    uint32_t boff = (uint32_t)((lane & 7) + ((lane & 16) ? 8 : 0)) * AP + ((lane & 8) ? 16 : 0);

    for (int c = 0; c < NCHUNK; c++) {
        if (c >= NCHUNK - 2) { CP_WAIT(0); } else { CP_WAIT(1); }
        __syncthreads();

        if (c + 2 < NCHUNK) ldA();           // LDG for chunk c+2; hidden by MMAs below

        uint32_t st = sb + (c & 1) * SSZ;
#pragma unroll
        for (int ks = 0; ks < 2; ks++) {
            uint32_t ahf[2][4], alf[2][4];
#pragma unroll
            for (int mf = 0; mf < 2; mf++) {
                uint32_t ra = st + (uint32_t)(warpM * 32 + mf * 16) * AP + aoff + ks * 32;
                ldm4(ahf[mf], ra);
                ldm4(alf[mf], ra + APA);
            }
#pragma unroll
            for (int p = 0; p < 4; p++) {
                uint32_t rbn = st + 2 * APA + (uint32_t)(warpN * 64 + p * 16) * AP + boff + ks * 32;
                uint32_t rh[4], rl[4];
                ldm4(rh, rbn);
                ldm4(rl, rbn + APB);
                uint32_t bh0[2] = { rh[0], rh[1] }, bh1[2] = { rh[2], rh[3] };
                uint32_t bl0[2] = { rl[0], rl[1] }, bl1[2] = { rl[2], rl[3] };
                mma_bf16(acc[0][2*p],   ahf[0], bh0);
                mma_bf16(acc[1][2*p],   ahf[1], bh0);
                mma_bf16(acc[0][2*p+1], ahf[0], bh1);
                mma_bf16(acc[1][2*p+1], ahf[1], bh1);

                mma_bf16(acc[0][2*p],   ahf[0], bl0);
                mma_bf16(acc[1][2*p],   ahf[1], bl0);
                mma_bf16(acc[0][2*p+1], ahf[0], bl1);
                mma_bf16(acc[1][2*p+1], ahf[1], bl1);

                mma_bf16(acc[0][2*p],   alf[0], bh0);
                mma_bf16(acc[1][2*p],   alf[1], bh0);
                mma_bf16(acc[0][2*p+1], alf[0], bh1);
                mma_bf16(acc[1][2*p+1], alf[1], bh1);
            }
        }

        if (c + 2 < NCHUNK) {
            __syncthreads();           // all LDSM reads of this stage done
            stA(c & 1);                // convert prefetched aR into freed stage
            cpB(c & 1);
        }
    }

    int g = lane >> 2, tt = lane & 3;
    if (m == 0) {
        // h_self straight to out
#pragma unroll
        for (int mf = 0; mf < 2; mf++)
#pragma unroll
            for (int nf = 0; nf < 8; nf++) {
                int r0 = rowBase + warpM * 32 + mf * 16 + g;
                int col = warpN * 64 + nf * 8 + tt * 2;
                if (r0 < NNODES)
                    *(float2*)&out[(size_t)r0 * 256 + col] = make_float2(acc[mf][nf][0], acc[mf][nf][1]);
                if (r0 + 8 < NNODES)
                    *(float2*)&out[(size_t)(r0 + 8) * 256 + col] = make_float2(acc[mf][nf][2], acc[mf][nf][3]);
            }
        return;
    }

    // h_neigh: stage into smem overlay, then top-32 via sorted shift-register + REDUX
    __syncthreads();
    float* stg = (float*)sm;                 // 64 rows x stride 258 floats
#pragma unroll
    for (int mf = 0; mf < 2; mf++)
#pragma unroll
        for (int nf = 0; nf < 8; nf++) {
            int lr = warpM * 32 + mf * 16 + g;
            int col = warpN * 64 + nf * 8 + tt * 2;
            *(float2*)&stg[(size_t)lr * 258 + col]       = make_float2(acc[mf][nf][0], acc[mf][nf][1]);
            *(float2*)&stg[(size_t)(lr + 8) * 258 + col] = make_float2(acc[mf][nf][2], acc[mf][nf][3]);
        }
    __syncthreads();

    int lr0 = w * 8;
    unsigned sk[8][8], win[8];
#define CE(r,i,j) { unsigned _a = sk[r][i], _b = sk[r][j]; \
                    sk[r][i] = _a > _b ? _a : _b; sk[r][j] = _a > _b ? _b : _a; }
#pragma unroll
    for (int r = 0; r < 8; r++) {
#pragma unroll
        for (int j = 0; j < 8; j++) {
            int col = j * 32 + lane;
            unsigned u = __float_as_uint(stg[(size_t)(lr0 + r) * 258 + col]);
            unsigned key = (u & 0x80000000u) ? ~u : (u | 0x80000000u);
            sk[r][j] = (key & 0xFFFFFF00u) | (255u - (unsigned)col);
        }
        // Batcher odd-even merge sort, 19 CE, descending
        CE(r,0,1) CE(r,2,3) CE(r,4,5) CE(r,6,7)
        CE(r,0,2) CE(r,1,3) CE(r,4,6) CE(r,5,7)
        CE(r,1,2) CE(r,5,6)
        CE(r,0,4) CE(r,1,5) CE(r,2,6) CE(r,3,7)
        CE(r,2,4) CE(r,3,5)
        CE(r,1,2) CE(r,3,4) CE(r,5,6)
        win[r] = 0;
    }
#undef CE

#pragma unroll 1
    for (int it = 0; it < MAXK; it++) {
        unsigned gm[8];
#pragma unroll
        for (int r = 0; r < 8; r++) gm[r] = __reduce_max_sync(0xFFFFFFFFu, sk[r][0]);
#pragma unroll
        for (int r = 0; r < 8; r++) {
            win[r] = (lane == it) ? gm[r] : win[r];
            bool own = (sk[r][0] == gm[r]);
#pragma unroll
            for (int j = 0; j < 7; j++) sk[r][j] = own ? sk[r][j + 1] : sk[r][j];
            sk[r][7] = own ? 0u : sk[r][7];
        }
    }

    // store packed (val_bits & 0xFFFFFF00) | col — ONE 4-byte word per entry
#pragma unroll
    for (int r = 0; r < 8; r++) {
        int grow = rowBase + lr0 + r;
        if (grow < NNODES) {
            unsigned col = 255u - (win[r] & 0xFFu);
            unsigned kk = win[r] & 0xFFFFFF00u;
            unsigned u = (kk & 0x80000000u) ? (kk & 0x7FFFFFFFu) : ~kk;
            g_pk[(size_t)grow * MAXK + lane] = (u & 0xFFFFFF00u) | col;
        }
    }
}

// ---------------- aggregation: one warp per dst node, packed single-word gather ----------------
__global__ __launch_bounds__(512) void k_aggregate(float* __restrict__ out) {
    __shared__ float acc[16][256];
    int w = threadIdx.x >> 5;
    int lane = threadIdx.x & 31;
    int v = blockIdx.x * 16 + w;
    if (v >= NNODES) return;

#pragma unroll
    for (int j = 0; j < 8; j++) acc[w][lane + 32 * j] = 0.f;
    __syncwarp();

    int beg = g_off[v];
    int end = g_off[v + 1];
    int c = 0; float vv = 0.f;
    if (beg < end) {
        int s = g_csr[beg];
        unsigned pk = g_pk[(size_t)s * MAXK + lane];
        c  = (int)(pk & 0xFFu);
        vv = __uint_as_float(pk & 0xFFFFFF00u);
    }
    for (int e = beg; e < end; e++) {
        int nc = 0; float nv = 0.f;
        if (e + 1 < end) {
            int s2 = g_csr[e + 1];
            unsigned pk = g_pk[(size_t)s2 * MAXK + lane];
            nc = (int)(pk & 0xFFu);
            nv = __uint_as_float(pk & 0xFFFFFF00u);
        }
        acc[w][c] += vv;          // distinct addrs within edge -> race-free
        __syncwarp();             // order before next edge's RMW
        c = nc; vv = nv;
    }

    int deg = end - beg;
    float inv = 1.0f / (float)(deg > 0 ? deg : 1);
    size_t bo = (size_t)v * FEATS;
#pragma unroll
    for (int j = 0; j < 8; j++) {
        int cc = lane + 32 * j;
        out[bo + cc] += acc[w][cc] * inv;
    }
}

// ---------------- launch: fork CSR-build chain onto a side stream; join before aggregate ----------------
extern "C" void kernel_launch(void* const* d_in, const int* in_sizes, int n_in,
                              void* d_out, int out_size) {
    const float* feat = (const float*)d_in[0];
    const float* Ws   = (const float*)d_in[1];
    const float* Wn   = (const float*)d_in[2];
    const void*  src  = d_in[3];
    const void*  dst  = d_in[4];
    float* out = (float*)d_out;

    cudaFuncSetAttribute(k_gemm, cudaFuncAttributeMaxDynamicSharedMemorySize, SMEM_DYN);

    cudaStream_t s2;
    cudaStreamCreateWithFlags(&s2, cudaStreamNonBlocking);
    cudaEvent_t eFork, eJoin;
    cudaEventCreateWithFlags(&eFork, cudaEventDisableTiming);
    cudaEventCreateWithFlags(&eJoin, cudaEventDisableTiming);

    // main chain (stream 0 / capture stream)
    k_prep_w<<<512, 256>>>(Ws, Wn);                           // 1st (also zeroes g_deg)

    // fork side chain (needs g_deg zeroed -> event after prep_w)
    cudaEventRecord(eFork, 0);
    cudaStreamWaitEvent(s2, eFork, 0);
    k_detect<<<1, 64, 0, s2>>>(src);                          // 2nd
    k_count<<<(NEDGES + 255) / 256, 256, 0, s2>>>(dst);       // 3rd

    dim3 gg(2, 1564);
    k_gemm<<<gg, 256, SMEM_DYN>>>(feat, out);                 // 4th launch (profiled)

    k_scan1<<<98, 1024, 0, s2>>>();
    k_scan2<<<1, 128, 0, s2>>>();
    k_scan3<<<98, 1024, 0, s2>>>();
    k_scatter<<<(NEDGES + 255) / 256, 256, 0, s2>>>(src, dst);

    // join: aggregate needs g_pk (stream 0) + g_csr/g_off (s2)
    cudaEventRecord(eJoin, s2);
    cudaStreamWaitEvent(0, eJoin, 0);
    k_aggregate<<<(NNODES + 15) / 16, 512>>>(out);

    cudaEventDestroy(eFork);
    cudaEventDestroy(eJoin);
    cudaStreamDestroy(s2);
}